// round 13
// baseline (speedup 1.0000x reference)
#include <cuda_runtime.h>
#include <math.h>
#include <stdint.h>

// Problem constants
#define SEQ   4096
#define BATCH 2
#define HID   2048
#define NHEADS 16
#define NKVH   4
#define HDIM   128
#define ROWS  (BATCH*SEQ)          // 8192
#define GRPSZ 1024
#define NGRP  4

// Scratch (no cudaMalloc allowed)
__device__ float g_Q[ROWS*HID];            // 64MB
__device__ float g_KV[ROWS*1024];          // 32MB: cols 0-511 K, 512-1023 V
__device__ float g_C[ROWS*HID];            // 64MB attention context (tf32-rounded)
__device__ float g_Xr[ROWS*HID];           // 64MB tf32-rounded hidden states
__device__ float g_Wq[HID*HID];            // 16MB rounded, [K,N]
__device__ float g_Wkv[HID*1024];          // 8MB rounded, cols 0-511 Wk, 512-1023 Wv
__device__ float g_Wo[HID*HID];            // 16MB

// ---------------------------------------------------------------------------
// Helpers
// ---------------------------------------------------------------------------
__device__ __forceinline__ uint32_t smem_u32(const void* p) {
    uint32_t a;
    asm("{ .reg .u64 t; cvta.to.shared.u64 t, %1; cvt.u32.u64 %0, t; }" : "=r"(a) : "l"(p));
    return a;
}
__device__ __forceinline__ float round_tf32(float x) {
    uint32_t u;
    asm("cvt.rna.tf32.f32 %0, %1;" : "=r"(u) : "f"(x));
    return __uint_as_float(u);
}
__device__ __forceinline__ void cp16(uint32_t dst, const void* src) {
    asm volatile("cp.async.cg.shared.global [%0], [%1], 16;" :: "r"(dst), "l"(src));
}
#define CP_COMMIT() asm volatile("cp.async.commit_group;" ::: "memory")
#define CP_WAIT0()  asm volatile("cp.async.wait_group 0;" ::: "memory")
__device__ __forceinline__ void mma1688(float* c, const uint32_t* a, const uint32_t* b) {
    asm volatile(
        "mma.sync.aligned.m16n8k8.row.col.f32.tf32.tf32.f32 "
        "{%0,%1,%2,%3}, {%4,%5,%6,%7}, {%8,%9}, {%0,%1,%2,%3};"
        : "+f"(c[0]), "+f"(c[1]), "+f"(c[2]), "+f"(c[3])
        : "r"(a[0]), "r"(a[1]), "r"(a[2]), "r"(a[3]), "r"(b[0]), "r"(b[1]));
}
__device__ __forceinline__ void st2_wt(float* p, float x, float y) {
    asm volatile("st.global.wt.v2.f32 [%0], {%1,%2};" :: "l"(p), "f"(x), "f"(y) : "memory");
}

// ---------------------------------------------------------------------------
// tf32 mma.sync GEMM: C[M,N] = A[M,K] @ B[K,N], row-major, K%32==0.
// CTA tile 128x128, BK=32, 3-stage cp.async pipeline, 8 warps at 64x32.
// rnd != 0: tf32-round outputs in the epilogue.
// ---------------------------------------------------------------------------
#define BM 128
#define BN 128
#define BK 32
#define AST 36
#define BST 136
#define A_BYTES (BM*AST*4)
#define B_BYTES (BK*BST*4)
#define STAGE_BYTES (A_BYTES + B_BYTES)
#define MMS_SMEM (3*STAGE_BYTES)          // 107520

__global__ void __launch_bounds__(256) mm_tf32s(const float* __restrict__ A,
                                                const float* __restrict__ B,
                                                float* __restrict__ C,
                                                int Ngl, int K, int rnd) {
    extern __shared__ float sm[];
    const uint32_t sb = smem_u32(sm);
    const int tid = threadIdx.x;
    const int wid = tid >> 5, lane = tid & 31;
    const int wm = wid >> 2, wn = wid & 3;
    const int g = lane >> 2, t = lane & 3;
    const int m0 = blockIdx.x * BM, n0 = blockIdx.y * BN;
    const float* Ag = A + (size_t)m0 * K;
    const float* Bg = B + n0;
    const int KT = K / BK;

    float acc[4][4][4];
#pragma unroll
    for (int i = 0; i < 4; i++)
#pragma unroll
        for (int j = 0; j < 4; j++)
#pragma unroll
            for (int q = 0; q < 4; q++) acc[i][j][q] = 0.f;

    auto load_stage = [&](int st, int kt) {
        uint32_t sA = sb + st * STAGE_BYTES;
        uint32_t sB = sA + A_BYTES;
#pragma unroll
        for (int l = 0; l < 4; l++) {
            int c = tid + l * 256;
            int r = c >> 3, kc = c & 7;
            cp16(sA + r * (AST * 4) + kc * 16, Ag + (size_t)r * K + kt * BK + kc * 4);
        }
#pragma unroll
        for (int l = 0; l < 4; l++) {
            int c = tid + l * 256;
            int r = c >> 5, nc = c & 31;
            cp16(sB + r * (BST * 4) + nc * 16, Bg + (size_t)(kt * BK + r) * Ngl + nc * 4);
        }
    };

    load_stage(0, 0);
    CP_COMMIT();
    load_stage(1, 1);
    CP_COMMIT();

    for (int kt = 0; kt < KT; kt++) {
        const int st = kt % 3;
        asm volatile("cp.async.wait_group 1;" ::: "memory");
        __syncthreads();

        if (kt + 2 < KT) load_stage((kt + 2) % 3, kt + 2);
        CP_COMMIT();

        const float* as = sm + st * (STAGE_BYTES / 4);
        const float* bs = as + A_BYTES / 4;
#pragma unroll
        for (int ks = 0; ks < 4; ks++) {
            const int k0 = ks * 8;
            uint32_t af[4][4], bf[4][2];
#pragma unroll
            for (int mt = 0; mt < 4; mt++) {
                int r0 = (wm * 64 + mt * 16 + g) * AST + k0 + t;
                af[mt][0] = __float_as_uint(as[r0]);
                af[mt][1] = __float_as_uint(as[r0 + 8 * AST]);
                af[mt][2] = __float_as_uint(as[r0 + 4]);
                af[mt][3] = __float_as_uint(as[r0 + 8 * AST + 4]);
            }
#pragma unroll
            for (int nt = 0; nt < 4; nt++) {
                int c0 = (k0 + t) * BST + wn * 32 + nt * 8 + g;
                bf[nt][0] = __float_as_uint(bs[c0]);
                bf[nt][1] = __float_as_uint(bs[c0 + 4 * BST]);
            }
#pragma unroll
            for (int mt = 0; mt < 4; mt++)
#pragma unroll
                for (int nt = 0; nt < 4; nt++)
                    mma1688(acc[mt][nt], af[mt], bf[nt]);
        }
        __syncthreads();
    }

#pragma unroll
    for (int mt = 0; mt < 4; mt++) {
#pragma unroll
        for (int nt = 0; nt < 4; nt++) {
            int row = m0 + wm * 64 + mt * 16 + g;
            int col = n0 + wn * 32 + nt * 8 + t * 2;
            float v0 = acc[mt][nt][0], v1 = acc[mt][nt][1];
            float v2 = acc[mt][nt][2], v3 = acc[mt][nt][3];
            if (rnd) {
                v0 = round_tf32(v0); v1 = round_tf32(v1);
                v2 = round_tf32(v2); v3 = round_tf32(v3);
            }
            st2_wt(&C[(size_t)row * Ngl + col], v0, v1);
            st2_wt(&C[(size_t)(row + 8) * Ngl + col], v2, v3);
        }
    }
}

// ---------------------------------------------------------------------------
// Elementwise tf32 round (vectorized)
// ---------------------------------------------------------------------------
__global__ void __launch_bounds__(256) round_x(float* __restrict__ dst,
                                               const float* __restrict__ src, int n4) {
    int i = blockIdx.x * blockDim.x + threadIdx.x;
    if (i >= n4) return;
    float4 v = ((const float4*)src)[i];
    v.x = round_tf32(v.x); v.y = round_tf32(v.y);
    v.z = round_tf32(v.z); v.w = round_tf32(v.w);
    ((float4*)dst)[i] = v;
}

// Round + interleave Wk|Wv into g_Wkv [2048][1024]
__global__ void __launch_bounds__(256) round_wkv(const float* __restrict__ Wk,
                                                 const float* __restrict__ Wv) {
    int i = blockIdx.x * blockDim.x + threadIdx.x;      // 262144 float4s each
    if (i >= HID * 512 / 4) return;
    int r = i >> 7, c4 = i & 127;                        // 128 float4 per 512-col row
    float4 a = ((const float4*)Wk)[i];
    a.x = round_tf32(a.x); a.y = round_tf32(a.y);
    a.z = round_tf32(a.z); a.w = round_tf32(a.w);
    ((float4*)g_Wkv)[(size_t)r * 256 + c4] = a;
    float4 b = ((const float4*)Wv)[i];
    b.x = round_tf32(b.x); b.y = round_tf32(b.y);
    b.z = round_tf32(b.z); b.w = round_tf32(b.w);
    ((float4*)g_Wkv)[(size_t)r * 256 + 128 + c4] = b;
}

// ---------------------------------------------------------------------------
// RoPE in-place on g_Q (16 heads, folds 1/sqrt(HD)) and K region of g_KV.
// Outputs tf32-rounded.
// ---------------------------------------------------------------------------
#define ATT_SCALE 0.08838834764831845f

__global__ void __launch_bounds__(256) rope_kernel(const int* __restrict__ pos_ids) {
    __shared__ double invs[64];
    if (threadIdx.x < 64)
        invs[threadIdx.x] = exp2(-(double)threadIdx.x * (13.287712379549449 / 64.0));
    __syncthreads();

    int gwarp = (blockIdx.x * blockDim.x + threadIdx.x) >> 5;
    int lane  = threadIdx.x & 31;
    if (gwarp >= ROWS * (NHEADS + NKVH)) return;
    int h   = gwarp % (NHEADS + NKVH);
    int row = gwarp / (NHEADS + NKVH);
    bool isq = (h < NHEADS);
    float* p = isq ? (g_Q + (size_t)row * HID + h * HDIM)
                   : (g_KV + (size_t)row * 1024 + (h - NHEADS) * HDIM);
    int ps = pos_ids[row];
    const double TWO_PI  = 6.283185307179586;
    const double INV_2PI = 0.15915494309189535;
    const float sc = isq ? ATT_SCALE : 1.0f;
#pragma unroll
    for (int jj = 0; jj < 2; jj++) {
        int j = lane + jj * 32;
        double ang = (double)ps * invs[j];
        ang -= floor(ang * INV_2PI) * TWO_PI;
        float s, c;
        sincosf((float)ang, &s, &c);
        float x0 = p[j], x1 = p[j + 64];
        p[j]      = round_tf32((x0 * c - x1 * s) * sc);
        p[j + 64] = round_tf32((x1 * c + x0 * s) * sc);
    }
}

// ---------------------------------------------------------------------------
// Flash attention, tf32 mma.sync, cp.async pipelined.
// CTA: 64 q-rows x head x group, 128 thr / 4 warps (16 q-rows each).
// K double-buffered (prefetch kt+1 during compute); V single-buffered
// (prefetch issued after PV sync). P fragments via shuffles (no smem).
// ---------------------------------------------------------------------------
#define KSTRIDE 132
#define VSTRIDE 136
#define ATT3_SMEM ((2*64*KSTRIDE + 64*VSTRIDE) * 4)   // 102400 bytes

__global__ void __launch_bounds__(128, 2) attn_mma() {
    extern __shared__ float smf[];
    float* Kb0 = smf;
    float* Kb1 = smf + 64 * KSTRIDE;
    float* Vs  = smf + 2 * 64 * KSTRIDE;
    const uint32_t sKb0 = smem_u32(Kb0);
    const uint32_t sKb1 = smem_u32(Kb1);
    const uint32_t sVs  = smem_u32(Vs);

    const int qt = 15 - blockIdx.x;
    const int h  = blockIdx.y;
    const int gi = blockIdx.z;
    const int b = gi >> 2, grp = gi & 3;
    const int kvh = h >> 2;
    const int shift = (h >= NHEADS / 2) ? (GRPSZ / 2) : 0;
    const int base = grp * GRPSZ + shift;
    const int tid = threadIdx.x, wid = tid >> 5, lane = tid & 31;
    const int g = lane >> 2, t = lane & 3;
    const int wr = wid * 16;

    // ---- Prologue: Q -> Kb1 via cp.async, lift fragments ----
#pragma unroll
    for (int l = 0; l < 16; l++) {
        int fid = tid + l * 128;
        int r = fid >> 5, d4 = (fid & 31) * 4;
        int srow = b * SEQ + ((base + qt * 64 + r) & (SEQ - 1));
        cp16(sKb1 + (r * KSTRIDE + d4) * 4, &g_Q[(size_t)srow * HID + h * HDIM + d4]);
    }
    CP_COMMIT();
    CP_WAIT0();
    __syncthreads();

    // issue K0 -> Kb0, V0 -> Vs (overlaps with qf lift below)
#pragma unroll
    for (int l = 0; l < 16; l++) {
        int fid = tid + l * 128;
        int r = fid >> 5, d4 = (fid & 31) * 4;
        int srow = b * SEQ + ((base + r) & (SEQ - 1));
        const float* kv = &g_KV[(size_t)srow * 1024 + kvh * HDIM + d4];
        cp16(sKb0 + (r * KSTRIDE + d4) * 4, kv);
        cp16(sVs  + (r * VSTRIDE + d4) * 4, kv + 512);
    }
    CP_COMMIT();

    uint32_t qf[16][4];
#pragma unroll
    for (int ks = 0; ks < 16; ks++) {
        int k0 = ks * 8;
        qf[ks][0] = __float_as_uint(Kb1[(wr + g) * KSTRIDE + k0 + t]);
        qf[ks][1] = __float_as_uint(Kb1[(wr + g + 8) * KSTRIDE + k0 + t]);
        qf[ks][2] = __float_as_uint(Kb1[(wr + g) * KSTRIDE + k0 + t + 4]);
        qf[ks][3] = __float_as_uint(Kb1[(wr + g + 8) * KSTRIDE + k0 + t + 4]);
    }

    float oacc[16][4];
#pragma unroll
    for (int nt = 0; nt < 16; nt++)
#pragma unroll
        for (int q = 0; q < 4; q++) oacc[nt][q] = 0.f;
    float m0 = -1e30f, m1 = -1e30f, l0 = 0.f, l1 = 0.f;
    const int row0 = qt * 64 + wr + g;
    const int row1 = row0 + 8;
    const unsigned FULL = 0xffffffffu;
    const int src0 = 4 * g + (t >> 1);
    const int src2 = src0 + 2;
    const bool thi = (t & 1);

    for (int kt = 0; kt <= qt; kt++) {
        CP_WAIT0();
        __syncthreads();
        const float* Ks = (kt & 1) ? Kb1 : Kb0;

        // prefetch K[kt+1] into the other K buffer (hidden under compute)
        if (kt < qt) {
            uint32_t dstK = (kt & 1) ? sKb0 : sKb1;
#pragma unroll
            for (int l = 0; l < 16; l++) {
                int fid = tid + l * 128;
                int r = fid >> 5, d4 = (fid & 31) * 4;
                int srow = b * SEQ + ((base + (kt + 1) * 64 + r) & (SEQ - 1));
                cp16(dstK + (r * KSTRIDE + d4) * 4,
                     &g_KV[(size_t)srow * 1024 + kvh * HDIM + d4]);
            }
            CP_COMMIT();
        }

        // ---- S = Q K^T ----
        float sa[8][4];
#pragma unroll
        for (int nt = 0; nt < 8; nt++) {
#pragma unroll
            for (int q = 0; q < 4; q++) sa[nt][q] = 0.f;
            const int c0 = nt * 8 + g;
#pragma unroll
            for (int ks = 0; ks < 16; ks++) {
                uint32_t bf[2];
                bf[0] = __float_as_uint(Ks[c0 * KSTRIDE + ks * 8 + t]);
                bf[1] = __float_as_uint(Ks[c0 * KSTRIDE + ks * 8 + t + 4]);
                mma1688(sa[nt], qf[ks], bf);
            }
        }

        // ---- Online softmax ----
        const bool diag = (kt == qt);
        float mx0 = -1e30f, mx1 = -1e30f;
#pragma unroll
        for (int nt = 0; nt < 8; nt++) {
            if (diag) {
                int col = kt * 64 + nt * 8 + 2 * t;
                if (col > row0)     sa[nt][0] = -1e30f;
                if (col + 1 > row0) sa[nt][1] = -1e30f;
                if (col > row1)     sa[nt][2] = -1e30f;
                if (col + 1 > row1) sa[nt][3] = -1e30f;
            }
            mx0 = fmaxf(mx0, fmaxf(sa[nt][0], sa[nt][1]));
            mx1 = fmaxf(mx1, fmaxf(sa[nt][2], sa[nt][3]));
        }
        mx0 = fmaxf(mx0, __shfl_xor_sync(FULL, mx0, 1));
        mx0 = fmaxf(mx0, __shfl_xor_sync(FULL, mx0, 2));
        mx1 = fmaxf(mx1, __shfl_xor_sync(FULL, mx1, 1));
        mx1 = fmaxf(mx1, __shfl_xor_sync(FULL, mx1, 2));
        float mn0 = fmaxf(m0, mx0), mn1 = fmaxf(m1, mx1);
        float cr0 = __expf(m0 - mn0), cr1 = __expf(m1 - mn1);
        m0 = mn0; m1 = mn1;

        float ps0 = 0.f, ps1 = 0.f;
#pragma unroll
        for (int nt = 0; nt < 8; nt++) {
            float p0 = __expf(sa[nt][0] - m0), p1 = __expf(sa[nt][1] - m0);
            float p2 = __expf(sa[nt][2] - m1), p3 = __expf(sa[nt][3] - m1);
            ps0 += p0 + p1; ps1 += p2 + p3;
            sa[nt][0] = round_tf32(p0); sa[nt][1] = round_tf32(p1);
            sa[nt][2] = round_tf32(p2); sa[nt][3] = round_tf32(p3);
        }
        ps0 += __shfl_xor_sync(FULL, ps0, 1);
        ps0 += __shfl_xor_sync(FULL, ps0, 2);
        ps1 += __shfl_xor_sync(FULL, ps1, 1);
        ps1 += __shfl_xor_sync(FULL, ps1, 2);
        l0 = l0 * cr0 + ps0; l1 = l1 * cr1 + ps1;
#pragma unroll
        for (int nt = 0; nt < 16; nt++) {
            oacc[nt][0] *= cr0; oacc[nt][1] *= cr0;
            oacc[nt][2] *= cr1; oacc[nt][3] *= cr1;
        }

        // ---- O += P V, P fragments via shuffles ----
#pragma unroll
        for (int ks = 0; ks < 8; ks++) {
            float f00 = __shfl_sync(FULL, sa[ks][0], src0);
            float f01 = __shfl_sync(FULL, sa[ks][1], src0);
            float f10 = __shfl_sync(FULL, sa[ks][2], src0);
            float f11 = __shfl_sync(FULL, sa[ks][3], src0);
            float f20 = __shfl_sync(FULL, sa[ks][0], src2);
            float f21 = __shfl_sync(FULL, sa[ks][1], src2);
            float f30 = __shfl_sync(FULL, sa[ks][2], src2);
            float f31 = __shfl_sync(FULL, sa[ks][3], src2);
            uint32_t pf[4];
            pf[0] = __float_as_uint(thi ? f01 : f00);
            pf[1] = __float_as_uint(thi ? f11 : f10);
            pf[2] = __float_as_uint(thi ? f21 : f20);
            pf[3] = __float_as_uint(thi ? f31 : f30);
            const int k0 = ks * 8;
#pragma unroll
            for (int nt = 0; nt < 16; nt++) {
                uint32_t bf[2];
                bf[0] = __float_as_uint(Vs[(k0 + t) * VSTRIDE + nt * 8 + g]);
                bf[1] = __float_as_uint(Vs[(k0 + t + 4) * VSTRIDE + nt * 8 + g]);
                mma1688(oacc[nt], pf, bf);
            }
        }
        __syncthreads();

        // prefetch V[kt+1] (exposed only across the iteration boundary)
        if (kt < qt) {
#pragma unroll
            for (int l = 0; l < 16; l++) {
                int fid = tid + l * 128;
                int r = fid >> 5, d4 = (fid & 31) * 4;
                int srow = b * SEQ + ((base + (kt + 1) * 64 + r) & (SEQ - 1));
                cp16(sVs + (r * VSTRIDE + d4) * 4,
                     &g_KV[(size_t)srow * 1024 + kvh * HDIM + 512 + d4]);
            }
            CP_COMMIT();
        }
    }

    // ---- Epilogue ----
    float inv0 = 1.f / l0, inv1 = 1.f / l1;
    int srow0 = b * SEQ + ((base + row0) & (SEQ - 1));
    int srow1 = b * SEQ + ((base + row1) & (SEQ - 1));
    float* o0 = &g_C[(size_t)srow0 * HID + h * HDIM];
    float* o1 = &g_C[(size_t)srow1 * HID + h * HDIM];
#pragma unroll
    for (int nt = 0; nt < 16; nt++) {
        int col = nt * 8 + 2 * t;
        *(float2*)&o0[col] = make_float2(round_tf32(oacc[nt][0] * inv0),
                                         round_tf32(oacc[nt][1] * inv0));
        *(float2*)&o1[col] = make_float2(round_tf32(oacc[nt][2] * inv1),
                                         round_tf32(oacc[nt][3] * inv1));
    }
}

// ---------------------------------------------------------------------------
extern "C" void kernel_launch(void* const* d_in, const int* in_sizes, int n_in,
                              void* d_out, int out_size) {
    const float* X   = (const float*)d_in[0];
    const int*   pos = (const int*)d_in[2];
    const float* Wq  = (const float*)d_in[3];
    const float* Wk  = (const float*)d_in[4];
    const float* Wv  = (const float*)d_in[5];
    const float* Wo  = (const float*)d_in[6];
    float* out = (float*)d_out;

    float *Qb, *KVb, *Cb, *Xr, *Wqr, *Wkvr, *Wor;
    cudaGetSymbolAddress((void**)&Qb, g_Q);
    cudaGetSymbolAddress((void**)&KVb, g_KV);
    cudaGetSymbolAddress((void**)&Cb, g_C);
    cudaGetSymbolAddress((void**)&Xr, g_Xr);
    cudaGetSymbolAddress((void**)&Wqr, g_Wq);
    cudaGetSymbolAddress((void**)&Wkvr, g_Wkv);
    cudaGetSymbolAddress((void**)&Wor, g_Wo);

    cudaFuncSetAttribute(attn_mma, cudaFuncAttributeMaxDynamicSharedMemorySize, ATT3_SMEM);
    cudaFuncSetAttribute(mm_tf32s, cudaFuncAttributeMaxDynamicSharedMemorySize, MMS_SMEM);

    // Prep: tf32-round X and weights
    round_x<<<(ROWS * HID / 4 + 255) / 256, 256>>>(Xr, X, ROWS * HID / 4);
    round_x<<<(HID * HID / 4 + 255) / 256, 256>>>(Wqr, Wq, HID * HID / 4);
    round_x<<<(HID * HID / 4 + 255) / 256, 256>>>(Wor, Wo, HID * HID / 4);
    round_wkv<<<(HID * 512 / 4 + 255) / 256, 256>>>(Wk, Wv);

    // Projections (tf32 mma.sync): Q (N=2048), fused KV (N=1024, rounded out)
    mm_tf32s<<<dim3(ROWS / 128, HID / 128), 256, MMS_SMEM>>>(Xr, Wqr, Qb, HID, HID, 0);
    mm_tf32s<<<dim3(ROWS / 128, 1024 / 128), 256, MMS_SMEM>>>(Xr, Wkvr, KVb, 1024, HID, 1);

    // RoPE on Q (folds scale) and K region of KV; outputs tf32-rounded
    rope_kernel<<<20480, 256>>>(pos);

    // Grouped shifted causal attention (tf32 mma.sync, pipelined)
    attn_mma<<<dim3(16, 16, 8), 128, ATT3_SMEM>>>();

    // Output projection
    mm_tf32s<<<dim3(ROWS / 128, HID / 128), 256, MMS_SMEM>>>(Cb, Wor, out, HID, HID, 0);
}

// round 14
// speedup vs baseline: 1.2157x; 1.2157x over previous
#include <cuda_runtime.h>
#include <math.h>
#include <stdint.h>

// Problem constants
#define SEQ   4096
#define BATCH 2
#define HID   2048
#define NHEADS 16
#define NKVH   4
#define HDIM   128
#define ROWS  (BATCH*SEQ)          // 8192
#define GRPSZ 1024
#define NGRP  4

// Scratch (no cudaMalloc allowed)
__device__ float g_Q[ROWS*HID];            // 64MB
__device__ float g_KV[ROWS*1024];          // 32MB: cols 0-511 K, 512-1023 V
__device__ float g_C[ROWS*HID];            // 64MB attention context (tf32-rounded)
__device__ float g_Xr[ROWS*HID];           // 64MB tf32-rounded hidden states
__device__ float g_Wq[HID*HID];            // 16MB rounded, [K,N]
__device__ float g_Wkv[HID*1024];          // 8MB rounded, cols 0-511 Wk, 512-1023 Wv
__device__ float g_Wo[HID*HID];            // 16MB
__device__ float2 g_rope[SEQ*64];          // 2MB cos/sin table per (pos, freq)

// ---------------------------------------------------------------------------
// Helpers
// ---------------------------------------------------------------------------
__device__ __forceinline__ uint32_t smem_u32(const void* p) {
    uint32_t a;
    asm("{ .reg .u64 t; cvta.to.shared.u64 t, %1; cvt.u32.u64 %0, t; }" : "=r"(a) : "l"(p));
    return a;
}
__device__ __forceinline__ float round_tf32(float x) {
    uint32_t u;
    asm("cvt.rna.tf32.f32 %0, %1;" : "=r"(u) : "f"(x));
    return __uint_as_float(u);
}
__device__ __forceinline__ void cp16(uint32_t dst, const void* src) {
    asm volatile("cp.async.cg.shared.global [%0], [%1], 16;" :: "r"(dst), "l"(src));
}
#define CP_COMMIT() asm volatile("cp.async.commit_group;" ::: "memory")
#define CP_WAIT0()  asm volatile("cp.async.wait_group 0;" ::: "memory")
__device__ __forceinline__ void mma1688(float* c, const uint32_t* a, const uint32_t* b) {
    asm volatile(
        "mma.sync.aligned.m16n8k8.row.col.f32.tf32.tf32.f32 "
        "{%0,%1,%2,%3}, {%4,%5,%6,%7}, {%8,%9}, {%0,%1,%2,%3};"
        : "+f"(c[0]), "+f"(c[1]), "+f"(c[2]), "+f"(c[3])
        : "r"(a[0]), "r"(a[1]), "r"(a[2]), "r"(a[3]), "r"(b[0]), "r"(b[1]));
}
__device__ __forceinline__ void st2_wt(float* p, float x, float y) {
    asm volatile("st.global.wt.v2.f32 [%0], {%1,%2};" :: "l"(p), "f"(x), "f"(y) : "memory");
}

// ---------------------------------------------------------------------------
// tf32 mma.sync GEMM: C[M,N] = A[M,K] @ B[K,N], row-major, K%32==0.
// CTA tile 128x128, BK=32, 3-stage cp.async pipeline.
// 4 warps (128 thr), warp tile 64x64 -> 8 MACs per smem byte (crossbar relief).
// rnd != 0: tf32-round outputs in the epilogue.
// ---------------------------------------------------------------------------
#define BM 128
#define BN 128
#define BK 32
#define AST 36
#define BST 136
#define A_BYTES (BM*AST*4)
#define B_BYTES (BK*BST*4)
#define STAGE_BYTES (A_BYTES + B_BYTES)
#define MMS_SMEM (3*STAGE_BYTES)          // 107520

__global__ void __launch_bounds__(128, 2) mm_tf32s(const float* __restrict__ A,
                                                   const float* __restrict__ B,
                                                   float* __restrict__ C,
                                                   int Ngl, int K, int rnd) {
    extern __shared__ float sm[];
    const uint32_t sb = smem_u32(sm);
    const int tid = threadIdx.x;
    const int wid = tid >> 5, lane = tid & 31;
    const int wm = wid >> 1, wn = wid & 1;       // 2x2 grid of 64x64 warp tiles
    const int g = lane >> 2, t = lane & 3;
    const int m0 = blockIdx.x * BM, n0 = blockIdx.y * BN;
    const float* Ag = A + (size_t)m0 * K;
    const float* Bg = B + n0;
    const int KT = K / BK;

    float acc[4][8][4];
#pragma unroll
    for (int i = 0; i < 4; i++)
#pragma unroll
        for (int j = 0; j < 8; j++)
#pragma unroll
            for (int q = 0; q < 4; q++) acc[i][j][q] = 0.f;

    auto load_stage = [&](int st, int kt) {
        uint32_t sA = sb + st * STAGE_BYTES;
        uint32_t sB = sA + A_BYTES;
#pragma unroll
        for (int l = 0; l < 8; l++) {           // A: 1024 16B chunks
            int c = tid + l * 128;
            int r = c >> 3, kc = c & 7;
            cp16(sA + r * (AST * 4) + kc * 16, Ag + (size_t)r * K + kt * BK + kc * 4);
        }
#pragma unroll
        for (int l = 0; l < 8; l++) {           // B: 1024 16B chunks
            int c = tid + l * 128;
            int r = c >> 5, nc = c & 31;
            cp16(sB + r * (BST * 4) + nc * 16, Bg + (size_t)(kt * BK + r) * Ngl + nc * 4);
        }
    };

    load_stage(0, 0);
    CP_COMMIT();
    load_stage(1, 1);
    CP_COMMIT();

    for (int kt = 0; kt < KT; kt++) {
        const int st = kt % 3;
        asm volatile("cp.async.wait_group 1;" ::: "memory");
        __syncthreads();

        if (kt + 2 < KT) load_stage((kt + 2) % 3, kt + 2);
        CP_COMMIT();

        const float* as = sm + st * (STAGE_BYTES / 4);
        const float* bs = as + A_BYTES / 4;
#pragma unroll
        for (int ks = 0; ks < 4; ks++) {
            const int k0 = ks * 8;
            uint32_t af[4][4], bf[8][2];
#pragma unroll
            for (int mt = 0; mt < 4; mt++) {
                int r0 = (wm * 64 + mt * 16 + g) * AST + k0 + t;
                af[mt][0] = __float_as_uint(as[r0]);
                af[mt][1] = __float_as_uint(as[r0 + 8 * AST]);
                af[mt][2] = __float_as_uint(as[r0 + 4]);
                af[mt][3] = __float_as_uint(as[r0 + 8 * AST + 4]);
            }
#pragma unroll
            for (int nt = 0; nt < 8; nt++) {
                int c0 = (k0 + t) * BST + wn * 64 + nt * 8 + g;
                bf[nt][0] = __float_as_uint(bs[c0]);
                bf[nt][1] = __float_as_uint(bs[c0 + 4 * BST]);
            }
#pragma unroll
            for (int mt = 0; mt < 4; mt++)
#pragma unroll
                for (int nt = 0; nt < 8; nt++)
                    mma1688(acc[mt][nt], af[mt], bf[nt]);
        }
        __syncthreads();
    }

#pragma unroll
    for (int mt = 0; mt < 4; mt++) {
#pragma unroll
        for (int nt = 0; nt < 8; nt++) {
            int row = m0 + wm * 64 + mt * 16 + g;
            int col = n0 + wn * 64 + nt * 8 + t * 2;
            float v0 = acc[mt][nt][0], v1 = acc[mt][nt][1];
            float v2 = acc[mt][nt][2], v3 = acc[mt][nt][3];
            if (rnd) {
                v0 = round_tf32(v0); v1 = round_tf32(v1);
                v2 = round_tf32(v2); v3 = round_tf32(v3);
            }
            st2_wt(&C[(size_t)row * Ngl + col], v0, v1);
            st2_wt(&C[(size_t)(row + 8) * Ngl + col], v2, v3);
        }
    }
}

// ---------------------------------------------------------------------------
// Elementwise tf32 round (vectorized)
// ---------------------------------------------------------------------------
__global__ void __launch_bounds__(256) round_x(float* __restrict__ dst,
                                               const float* __restrict__ src, int n4) {
    int i = blockIdx.x * blockDim.x + threadIdx.x;
    if (i >= n4) return;
    float4 v = ((const float4*)src)[i];
    v.x = round_tf32(v.x); v.y = round_tf32(v.y);
    v.z = round_tf32(v.z); v.w = round_tf32(v.w);
    ((float4*)dst)[i] = v;
}

// Round + interleave Wk|Wv into g_Wkv [2048][1024]
__global__ void __launch_bounds__(256) round_wkv(const float* __restrict__ Wk,
                                                 const float* __restrict__ Wv) {
    int i = blockIdx.x * blockDim.x + threadIdx.x;
    if (i >= HID * 512 / 4) return;
    int r = i >> 7, c4 = i & 127;
    float4 a = ((const float4*)Wk)[i];
    a.x = round_tf32(a.x); a.y = round_tf32(a.y);
    a.z = round_tf32(a.z); a.w = round_tf32(a.w);
    ((float4*)g_Wkv)[(size_t)r * 256 + c4] = a;
    float4 b = ((const float4*)Wv)[i];
    b.x = round_tf32(b.x); b.y = round_tf32(b.y);
    b.z = round_tf32(b.z); b.w = round_tf32(b.w);
    ((float4*)g_Wkv)[(size_t)r * 256 + 128 + c4] = b;
}

// ---------------------------------------------------------------------------
// RoPE: precompute cos/sin table (double-accurate, done once: 256K entries),
// then a pure-fp32 streaming pass applies it to Q (folds 1/sqrt(HD)) and K.
// ---------------------------------------------------------------------------
#define ATT_SCALE 0.08838834764831845f

__global__ void __launch_bounds__(256) rope_table() {
    int idx = blockIdx.x * 256 + threadIdx.x;          // 262144
    int pos = idx >> 6, j = idx & 63;
    double inv = exp2(-(double)j * (13.287712379549449 / 64.0));
    double ang = (double)pos * inv;
    ang -= floor(ang * 0.15915494309189535) * 6.283185307179586;
    float s, c;
    sincosf((float)ang, &s, &c);
    g_rope[idx] = make_float2(c, s);
}

__global__ void __launch_bounds__(256) rope_kernel(const int* __restrict__ pos_ids) {
    int gwarp = (blockIdx.x * blockDim.x + threadIdx.x) >> 5;
    int lane  = threadIdx.x & 31;
    if (gwarp >= ROWS * (NHEADS + NKVH)) return;
    int h   = gwarp % (NHEADS + NKVH);
    int row = gwarp / (NHEADS + NKVH);
    bool isq = (h < NHEADS);
    float* p = isq ? (g_Q + (size_t)row * HID + h * HDIM)
                   : (g_KV + (size_t)row * 1024 + (h - NHEADS) * HDIM);
    int ps = pos_ids[row] & (SEQ - 1);
    const float sc = isq ? ATT_SCALE : 1.0f;
#pragma unroll
    for (int jj = 0; jj < 2; jj++) {
        int j = lane + jj * 32;
        float2 cs = g_rope[ps * 64 + j];
        float x0 = p[j], x1 = p[j + 64];
        p[j]      = round_tf32((x0 * cs.x - x1 * cs.y) * sc);
        p[j + 64] = round_tf32((x1 * cs.x + x0 * cs.y) * sc);
    }
}

// ---------------------------------------------------------------------------
// Flash attention, tf32 mma.sync, cp.async pipelined (unchanged from R13).
// ---------------------------------------------------------------------------
#define KSTRIDE 132
#define VSTRIDE 136
#define ATT3_SMEM ((2*64*KSTRIDE + 64*VSTRIDE) * 4)   // 102400 bytes

__global__ void __launch_bounds__(128, 2) attn_mma() {
    extern __shared__ float smf[];
    float* Kb0 = smf;
    float* Kb1 = smf + 64 * KSTRIDE;
    float* Vs  = smf + 2 * 64 * KSTRIDE;
    const uint32_t sKb0 = smem_u32(Kb0);
    const uint32_t sKb1 = smem_u32(Kb1);
    const uint32_t sVs  = smem_u32(Vs);

    const int qt = 15 - blockIdx.x;
    const int h  = blockIdx.y;
    const int gi = blockIdx.z;
    const int b = gi >> 2, grp = gi & 3;
    const int kvh = h >> 2;
    const int shift = (h >= NHEADS / 2) ? (GRPSZ / 2) : 0;
    const int base = grp * GRPSZ + shift;
    const int tid = threadIdx.x, wid = tid >> 5, lane = tid & 31;
    const int g = lane >> 2, t = lane & 3;
    const int wr = wid * 16;

    // ---- Prologue: Q -> Kb1 via cp.async, lift fragments ----
#pragma unroll
    for (int l = 0; l < 16; l++) {
        int fid = tid + l * 128;
        int r = fid >> 5, d4 = (fid & 31) * 4;
        int srow = b * SEQ + ((base + qt * 64 + r) & (SEQ - 1));
        cp16(sKb1 + (r * KSTRIDE + d4) * 4, &g_Q[(size_t)srow * HID + h * HDIM + d4]);
    }
    CP_COMMIT();
    CP_WAIT0();
    __syncthreads();

    // issue K0 -> Kb0, V0 -> Vs
#pragma unroll
    for (int l = 0; l < 16; l++) {
        int fid = tid + l * 128;
        int r = fid >> 5, d4 = (fid & 31) * 4;
        int srow = b * SEQ + ((base + r) & (SEQ - 1));
        const float* kv = &g_KV[(size_t)srow * 1024 + kvh * HDIM + d4];
        cp16(sKb0 + (r * KSTRIDE + d4) * 4, kv);
        cp16(sVs  + (r * VSTRIDE + d4) * 4, kv + 512);
    }
    CP_COMMIT();

    uint32_t qf[16][4];
#pragma unroll
    for (int ks = 0; ks < 16; ks++) {
        int k0 = ks * 8;
        qf[ks][0] = __float_as_uint(Kb1[(wr + g) * KSTRIDE + k0 + t]);
        qf[ks][1] = __float_as_uint(Kb1[(wr + g + 8) * KSTRIDE + k0 + t]);
        qf[ks][2] = __float_as_uint(Kb1[(wr + g) * KSTRIDE + k0 + t + 4]);
        qf[ks][3] = __float_as_uint(Kb1[(wr + g + 8) * KSTRIDE + k0 + t + 4]);
    }

    float oacc[16][4];
#pragma unroll
    for (int nt = 0; nt < 16; nt++)
#pragma unroll
        for (int q = 0; q < 4; q++) oacc[nt][q] = 0.f;
    float m0 = -1e30f, m1 = -1e30f, l0 = 0.f, l1 = 0.f;
    const int row0 = qt * 64 + wr + g;
    const int row1 = row0 + 8;
    const unsigned FULL = 0xffffffffu;
    const int src0 = 4 * g + (t >> 1);
    const int src2 = src0 + 2;
    const bool thi = (t & 1);

    for (int kt = 0; kt <= qt; kt++) {
        CP_WAIT0();
        __syncthreads();
        const float* Ks = (kt & 1) ? Kb1 : Kb0;

        if (kt < qt) {
            uint32_t dstK = (kt & 1) ? sKb0 : sKb1;
#pragma unroll
            for (int l = 0; l < 16; l++) {
                int fid = tid + l * 128;
                int r = fid >> 5, d4 = (fid & 31) * 4;
                int srow = b * SEQ + ((base + (kt + 1) * 64 + r) & (SEQ - 1));
                cp16(dstK + (r * KSTRIDE + d4) * 4,
                     &g_KV[(size_t)srow * 1024 + kvh * HDIM + d4]);
            }
            CP_COMMIT();
        }

        // ---- S = Q K^T ----
        float sa[8][4];
#pragma unroll
        for (int nt = 0; nt < 8; nt++) {
#pragma unroll
            for (int q = 0; q < 4; q++) sa[nt][q] = 0.f;
            const int c0 = nt * 8 + g;
#pragma unroll
            for (int ks = 0; ks < 16; ks++) {
                uint32_t bf[2];
                bf[0] = __float_as_uint(Ks[c0 * KSTRIDE + ks * 8 + t]);
                bf[1] = __float_as_uint(Ks[c0 * KSTRIDE + ks * 8 + t + 4]);
                mma1688(sa[nt], qf[ks], bf);
            }
        }

        // ---- Online softmax ----
        const bool diag = (kt == qt);
        float mx0 = -1e30f, mx1 = -1e30f;
#pragma unroll
        for (int nt = 0; nt < 8; nt++) {
            if (diag) {
                int col = kt * 64 + nt * 8 + 2 * t;
                if (col > row0)     sa[nt][0] = -1e30f;
                if (col + 1 > row0) sa[nt][1] = -1e30f;
                if (col > row1)     sa[nt][2] = -1e30f;
                if (col + 1 > row1) sa[nt][3] = -1e30f;
            }
            mx0 = fmaxf(mx0, fmaxf(sa[nt][0], sa[nt][1]));
            mx1 = fmaxf(mx1, fmaxf(sa[nt][2], sa[nt][3]));
        }
        mx0 = fmaxf(mx0, __shfl_xor_sync(FULL, mx0, 1));
        mx0 = fmaxf(mx0, __shfl_xor_sync(FULL, mx0, 2));
        mx1 = fmaxf(mx1, __shfl_xor_sync(FULL, mx1, 1));
        mx1 = fmaxf(mx1, __shfl_xor_sync(FULL, mx1, 2));
        float mn0 = fmaxf(m0, mx0), mn1 = fmaxf(m1, mx1);
        float cr0 = __expf(m0 - mn0), cr1 = __expf(m1 - mn1);
        m0 = mn0; m1 = mn1;

        float ps0 = 0.f, ps1 = 0.f;
#pragma unroll
        for (int nt = 0; nt < 8; nt++) {
            float p0 = __expf(sa[nt][0] - m0), p1 = __expf(sa[nt][1] - m0);
            float p2 = __expf(sa[nt][2] - m1), p3 = __expf(sa[nt][3] - m1);
            ps0 += p0 + p1; ps1 += p2 + p3;
            sa[nt][0] = round_tf32(p0); sa[nt][1] = round_tf32(p1);
            sa[nt][2] = round_tf32(p2); sa[nt][3] = round_tf32(p3);
        }
        ps0 += __shfl_xor_sync(FULL, ps0, 1);
        ps0 += __shfl_xor_sync(FULL, ps0, 2);
        ps1 += __shfl_xor_sync(FULL, ps1, 1);
        ps1 += __shfl_xor_sync(FULL, ps1, 2);
        l0 = l0 * cr0 + ps0; l1 = l1 * cr1 + ps1;
#pragma unroll
        for (int nt = 0; nt < 16; nt++) {
            oacc[nt][0] *= cr0; oacc[nt][1] *= cr0;
            oacc[nt][2] *= cr1; oacc[nt][3] *= cr1;
        }

        // ---- O += P V, P fragments via shuffles ----
#pragma unroll
        for (int ks = 0; ks < 8; ks++) {
            float f00 = __shfl_sync(FULL, sa[ks][0], src0);
            float f01 = __shfl_sync(FULL, sa[ks][1], src0);
            float f10 = __shfl_sync(FULL, sa[ks][2], src0);
            float f11 = __shfl_sync(FULL, sa[ks][3], src0);
            float f20 = __shfl_sync(FULL, sa[ks][0], src2);
            float f21 = __shfl_sync(FULL, sa[ks][1], src2);
            float f30 = __shfl_sync(FULL, sa[ks][2], src2);
            float f31 = __shfl_sync(FULL, sa[ks][3], src2);
            uint32_t pf[4];
            pf[0] = __float_as_uint(thi ? f01 : f00);
            pf[1] = __float_as_uint(thi ? f11 : f10);
            pf[2] = __float_as_uint(thi ? f21 : f20);
            pf[3] = __float_as_uint(thi ? f31 : f30);
            const int k0 = ks * 8;
#pragma unroll
            for (int nt = 0; nt < 16; nt++) {
                uint32_t bf[2];
                bf[0] = __float_as_uint(Vs[(k0 + t) * VSTRIDE + nt * 8 + g]);
                bf[1] = __float_as_uint(Vs[(k0 + t + 4) * VSTRIDE + nt * 8 + g]);
                mma1688(oacc[nt], pf, bf);
            }
        }
        __syncthreads();

        if (kt < qt) {
#pragma unroll
            for (int l = 0; l < 16; l++) {
                int fid = tid + l * 128;
                int r = fid >> 5, d4 = (fid & 31) * 4;
                int srow = b * SEQ + ((base + (kt + 1) * 64 + r) & (SEQ - 1));
                cp16(sVs + (r * VSTRIDE + d4) * 4,
                     &g_KV[(size_t)srow * 1024 + kvh * HDIM + 512 + d4]);
            }
            CP_COMMIT();
        }
    }

    // ---- Epilogue ----
    float inv0 = 1.f / l0, inv1 = 1.f / l1;
    int srow0 = b * SEQ + ((base + row0) & (SEQ - 1));
    int srow1 = b * SEQ + ((base + row1) & (SEQ - 1));
    float* o0 = &g_C[(size_t)srow0 * HID + h * HDIM];
    float* o1 = &g_C[(size_t)srow1 * HID + h * HDIM];
#pragma unroll
    for (int nt = 0; nt < 16; nt++) {
        int col = nt * 8 + 2 * t;
        *(float2*)&o0[col] = make_float2(round_tf32(oacc[nt][0] * inv0),
                                         round_tf32(oacc[nt][1] * inv0));
        *(float2*)&o1[col] = make_float2(round_tf32(oacc[nt][2] * inv1),
                                         round_tf32(oacc[nt][3] * inv1));
    }
}

// ---------------------------------------------------------------------------
extern "C" void kernel_launch(void* const* d_in, const int* in_sizes, int n_in,
                              void* d_out, int out_size) {
    const float* X   = (const float*)d_in[0];
    const int*   pos = (const int*)d_in[2];
    const float* Wq  = (const float*)d_in[3];
    const float* Wk  = (const float*)d_in[4];
    const float* Wv  = (const float*)d_in[5];
    const float* Wo  = (const float*)d_in[6];
    float* out = (float*)d_out;

    float *Qb, *KVb, *Cb, *Xr, *Wqr, *Wkvr, *Wor;
    cudaGetSymbolAddress((void**)&Qb, g_Q);
    cudaGetSymbolAddress((void**)&KVb, g_KV);
    cudaGetSymbolAddress((void**)&Cb, g_C);
    cudaGetSymbolAddress((void**)&Xr, g_Xr);
    cudaGetSymbolAddress((void**)&Wqr, g_Wq);
    cudaGetSymbolAddress((void**)&Wkvr, g_Wkv);
    cudaGetSymbolAddress((void**)&Wor, g_Wo);

    cudaFuncSetAttribute(attn_mma, cudaFuncAttributeMaxDynamicSharedMemorySize, ATT3_SMEM);
    cudaFuncSetAttribute(mm_tf32s, cudaFuncAttributeMaxDynamicSharedMemorySize, MMS_SMEM);

    // Prep: rope table + tf32-round X and weights
    rope_table<<<1024, 256>>>();
    round_x<<<(ROWS * HID / 4 + 255) / 256, 256>>>(Xr, X, ROWS * HID / 4);
    round_x<<<(HID * HID / 4 + 255) / 256, 256>>>(Wqr, Wq, HID * HID / 4);
    round_x<<<(HID * HID / 4 + 255) / 256, 256>>>(Wor, Wo, HID * HID / 4);
    round_wkv<<<(HID * 512 / 4 + 255) / 256, 256>>>(Wk, Wv);

    // Projections (tf32 mma.sync): Q (N=2048), fused KV (N=1024, rounded out)
    mm_tf32s<<<dim3(ROWS / 128, HID / 128), 128, MMS_SMEM>>>(Xr, Wqr, Qb, HID, HID, 0);
    mm_tf32s<<<dim3(ROWS / 128, 1024 / 128), 128, MMS_SMEM>>>(Xr, Wkvr, KVb, 1024, HID, 1);

    // RoPE on Q (folds scale) and K region of KV; outputs tf32-rounded
    rope_kernel<<<20480, 256>>>(pos);

    // Grouped shifted causal attention (tf32 mma.sync, pipelined)
    attn_mma<<<dim3(16, 16, 8), 128, ATT3_SMEM>>>();

    // Output projection
    mm_tf32s<<<dim3(ROWS / 128, HID / 128), 128, MMS_SMEM>>>(Cb, Wor, out, HID, HID, 0);
}